// round 9
// baseline (speedup 1.0000x reference)
#include <cuda_runtime.h>

// QSoftmax: out = clip(rint((LUT[inp] - exp_zero) * (1/rowsum(LUT[inp]) - 1/exp_zero)
//                           * (exp_scale * (1/exp_scale) / normed_scale) + normed_zero), 0, 255)
// inp: int32 [8, 2048, 2048], LUT: float32 [256], 4 scalar float params, out: float32.
//
// R9: 8 rows per CTA, software-pipelined int4 loads, 32-way replicated LUT in
// shared memory (gather address = idx*32 + lane -> bank == lane, conflict-free),
// one barrier per row via double-buffered cross-warp partials.

#define S_LEN 2048
#define THREADS 256
#define PER_THREAD 8            // 2048 / 256
#define ROWS_PER_CTA 8
#define ROW_STRIDE_I4 (S_LEN / 4)   // 512 int4 per row

__global__ __launch_bounds__(THREADS)
void qsoftmax_kernel(const int* __restrict__ inp,
                     const float* __restrict__ lut,
                     const float* __restrict__ exp_scale_p,
                     const float* __restrict__ exp_zero_p,
                     const float* __restrict__ normed_scale_p,
                     const float* __restrict__ normed_zero_p,
                     float* __restrict__ out)
{
    // 32-way replicated LUT: slut[idx*32 + lane]. 256 entries * 32 lanes * 4B = 32KB.
    __shared__ float slut[256 * 32];
    __shared__ float swsum[2][THREADS / 32];

    const int tid  = threadIdx.x;
    const int lane = tid & 31;
    const int wid  = tid >> 5;

    // Init replicated LUT: consecutive tids write consecutive words (no ST conflicts);
    // 8 adjacent threads share one LUT entry (L1-hit reloads).
    #pragma unroll
    for (int i = tid; i < 256 * 32; i += THREADS)
        slut[i] = __ldg(&lut[i >> 5]);

    // Scalar params (L2 hits, overlap with LUT init)
    const float exp_scale    = exp_scale_p[0];
    const float exp_zero     = exp_zero_p[0];
    const float normed_scale = normed_scale_p[0];
    const float normed_zero  = normed_zero_p[0];

    const float inv_ez     = 1.0f / exp_zero;
    const float multiplier = exp_scale * (1.0f / exp_scale) / normed_scale;

    __syncthreads();

    const long long base = (long long)blockIdx.x * (ROWS_PER_CTA * S_LEN)
                         + (long long)tid * PER_THREAD;
    const int4*  in4  = reinterpret_cast<const int4*>(inp + base);
    float4*      out4 = reinterpret_cast<float4*>(out + base);

    // Prime the pipeline: row 0 loads
    int4 a = in4[0];
    int4 b = in4[1];

    #pragma unroll
    for (int r = 0; r < ROWS_PER_CTA; ++r) {
        // Prefetch next row's input before this row's reduction stalls us.
        int4 an, bn;
        if (r + 1 < ROWS_PER_CTA) {
            an = in4[(r + 1) * ROW_STRIDE_I4];
            bn = in4[(r + 1) * ROW_STRIDE_I4 + 1];
        }

        // Conflict-free gathers: bank == lane for every access.
        float e0 = slut[(a.x << 5) + lane];
        float e1 = slut[(a.y << 5) + lane];
        float e2 = slut[(a.z << 5) + lane];
        float e3 = slut[(a.w << 5) + lane];
        float e4 = slut[(b.x << 5) + lane];
        float e5 = slut[(b.y << 5) + lane];
        float e6 = slut[(b.z << 5) + lane];
        float e7 = slut[(b.w << 5) + lane];

        float s = ((e0 + e1) + (e2 + e3)) + ((e4 + e5) + (e6 + e7));

        #pragma unroll
        for (int off = 16; off > 0; off >>= 1)
            s += __shfl_xor_sync(0xffffffffu, s, off);

        if (lane == 0) swsum[r & 1][wid] = s;
        __syncthreads();

        const float* ws = swsum[r & 1];
        float rowsum = ((ws[0] + ws[1]) + (ws[2] + ws[3]))
                     + ((ws[4] + ws[5]) + (ws[6] + ws[7]));

        const float factor = (1.0f / rowsum - inv_ez) * multiplier;

        float4 o0, o1;
        o0.x = fminf(fmaxf(rintf((e0 - exp_zero) * factor + normed_zero), 0.0f), 255.0f);
        o0.y = fminf(fmaxf(rintf((e1 - exp_zero) * factor + normed_zero), 0.0f), 255.0f);
        o0.z = fminf(fmaxf(rintf((e2 - exp_zero) * factor + normed_zero), 0.0f), 255.0f);
        o0.w = fminf(fmaxf(rintf((e3 - exp_zero) * factor + normed_zero), 0.0f), 255.0f);
        o1.x = fminf(fmaxf(rintf((e4 - exp_zero) * factor + normed_zero), 0.0f), 255.0f);
        o1.y = fminf(fmaxf(rintf((e5 - exp_zero) * factor + normed_zero), 0.0f), 255.0f);
        o1.z = fminf(fmaxf(rintf((e6 - exp_zero) * factor + normed_zero), 0.0f), 255.0f);
        o1.w = fminf(fmaxf(rintf((e7 - exp_zero) * factor + normed_zero), 0.0f), 255.0f);

        out4[r * ROW_STRIDE_I4]     = o0;
        out4[r * ROW_STRIDE_I4 + 1] = o1;

        a = an;
        b = bn;
    }
}

extern "C" void kernel_launch(void* const* d_in, const int* in_sizes, int n_in,
                              void* d_out, int out_size)
{
    const int*   inp          = (const int*)d_in[0];
    const float* lut          = (const float*)d_in[1];
    const float* exp_scale    = (const float*)d_in[2];
    const float* exp_zero     = (const float*)d_in[3];
    const float* normed_scale = (const float*)d_in[4];
    const float* normed_zero  = (const float*)d_in[5];
    float*       out          = (float*)d_out;

    const int num_rows = out_size / S_LEN;             // 16384
    const int blocks   = num_rows / ROWS_PER_CTA;      // 2048
    qsoftmax_kernel<<<blocks, THREADS>>>(inp, lut, exp_scale, exp_zero,
                                         normed_scale, normed_zero, out);
}

// round 10
// speedup vs baseline: 1.3132x; 1.3132x over previous
#include <cuda_runtime.h>
#include <math.h>

// QSoftmax: out = clip(rint((LUT[inp]-exp_zero) * (1/rowsum(LUT[inp]) - 1/exp_zero)
//                           * (exp_scale*(1/exp_scale)/normed_scale) + normed_zero), 0, 255)
//
// R10: algebraic fast path. Whenever the runtime-checked invariants
//   (1) LUT[i] >= exp_zero for all i   (=> a_zeroed >= 0; NaN entries fail this)
//   (2) exp_zero > 0 and 1/exp_zero finite
//   (3) multiplier finite and > 0
//   (4) normed_zero < 0.5
// hold, then rowsum >= 2048*exp_zero > exp_zero => b_zeroed < 0, so
// r = a_zeroed*b_zeroed*multiplier + normed_zero <= normed_zero < 0.5
// => rint(r) <= 0 => clip(...) == 0 for EVERY element, independent of inp.
// (inf LUT entries give r = -inf -> clip 0 in reference too.)
// Fast path: write-only zero fill (no input read). Otherwise: general
// single-pass kernel (the proven R8 version).

#define S_LEN 2048
#define THREADS 256
#define PER_THREAD 8   // 2048 / 256

__device__ int g_allzero_flag;

// ---------------------------------------------------------------- predicate
__global__ void qsoftmax_predicate(const float* __restrict__ lut,
                                   const float* __restrict__ exp_scale_p,
                                   const float* __restrict__ exp_zero_p,
                                   const float* __restrict__ normed_scale_p,
                                   const float* __restrict__ normed_zero_p)
{
    const int t = threadIdx.x;  // 256 threads, one LUT entry each
    const float exp_zero     = exp_zero_p[0];
    const float exp_scale    = exp_scale_p[0];
    const float normed_scale = normed_scale_p[0];
    const float normed_zero  = normed_zero_p[0];

    const float v = lut[t];
    int ok = (v >= exp_zero) ? 1 : 0;          // false for NaN entries

    const float inv_ez = 1.0f / exp_zero;
    const float mult   = exp_scale * (1.0f / exp_scale) / normed_scale;

    ok = ok && (exp_zero > 0.0f)
            && isfinite(inv_ez)
            && isfinite(mult) && (mult > 0.0f)
            && (normed_zero < 0.5f);           // false for NaN normed_zero

    ok = __syncthreads_and(ok);
    if (t == 0) g_allzero_flag = ok;
}

// ---------------------------------------------------------------- zero fill
__global__ __launch_bounds__(THREADS, 8)
void qsoftmax_zero_fill(float* __restrict__ out, long long n4)
{
    if (!g_allzero_flag) return;  // general kernel will handle it
    const float4 z = make_float4(0.0f, 0.0f, 0.0f, 0.0f);
    float4* o4 = reinterpret_cast<float4*>(out);
    long long i = (long long)blockIdx.x * blockDim.x + threadIdx.x;
    const long long stride = (long long)gridDim.x * blockDim.x;
    for (; i < n4; i += stride)
        o4[i] = z;
}

// ---------------------------------------------------------------- general path
__global__ __launch_bounds__(THREADS, 8)
void qsoftmax_general(const int* __restrict__ inp,
                      const float* __restrict__ lut,
                      const float* __restrict__ exp_scale_p,
                      const float* __restrict__ exp_zero_p,
                      const float* __restrict__ normed_scale_p,
                      const float* __restrict__ normed_zero_p,
                      float* __restrict__ out)
{
    if (g_allzero_flag) return;   // fast path already wrote the output

    __shared__ float slut[256];
    __shared__ float swsum[THREADS / 32];

    const int tid = threadIdx.x;
    slut[tid] = lut[tid];
    __syncthreads();

    const long long base = (long long)blockIdx.x * S_LEN + (long long)tid * PER_THREAD;

    const int4* in4 = reinterpret_cast<const int4*>(inp + base);
    int4 a = in4[0];
    int4 b = in4[1];

    float e[PER_THREAD];
    e[0] = slut[a.x]; e[1] = slut[a.y]; e[2] = slut[a.z]; e[3] = slut[a.w];
    e[4] = slut[b.x]; e[5] = slut[b.y]; e[6] = slut[b.z]; e[7] = slut[b.w];

    float s = ((e[0] + e[1]) + (e[2] + e[3])) + ((e[4] + e[5]) + (e[6] + e[7]));

    #pragma unroll
    for (int off = 16; off > 0; off >>= 1)
        s += __shfl_xor_sync(0xffffffffu, s, off);

    const int wid = tid >> 5;
    if ((tid & 31) == 0) swsum[wid] = s;
    __syncthreads();

    float rowsum = ((swsum[0] + swsum[1]) + (swsum[2] + swsum[3]))
                 + ((swsum[4] + swsum[5]) + (swsum[6] + swsum[7]));

    const float exp_scale    = exp_scale_p[0];
    const float exp_zero     = exp_zero_p[0];
    const float normed_scale = normed_scale_p[0];
    const float normed_zero  = normed_zero_p[0];

    const float denom      = 1.0f / rowsum;
    const float multiplier = exp_scale * (1.0f / exp_scale) / normed_scale;
    const float b_zeroed   = denom - 1.0f / exp_zero;
    const float factor     = b_zeroed * multiplier;

    float4 o0, o1;
    o0.x = fminf(fmaxf(rintf((e[0] - exp_zero) * factor + normed_zero), 0.0f), 255.0f);
    o0.y = fminf(fmaxf(rintf((e[1] - exp_zero) * factor + normed_zero), 0.0f), 255.0f);
    o0.z = fminf(fmaxf(rintf((e[2] - exp_zero) * factor + normed_zero), 0.0f), 255.0f);
    o0.w = fminf(fmaxf(rintf((e[3] - exp_zero) * factor + normed_zero), 0.0f), 255.0f);
    o1.x = fminf(fmaxf(rintf((e[4] - exp_zero) * factor + normed_zero), 0.0f), 255.0f);
    o1.y = fminf(fmaxf(rintf((e[5] - exp_zero) * factor + normed_zero), 0.0f), 255.0f);
    o1.z = fminf(fmaxf(rintf((e[6] - exp_zero) * factor + normed_zero), 0.0f), 255.0f);
    o1.w = fminf(fmaxf(rintf((e[7] - exp_zero) * factor + normed_zero), 0.0f), 255.0f);

    float4* out4 = reinterpret_cast<float4*>(out + base);
    out4[0] = o0;
    out4[1] = o1;
}

// ---------------------------------------------------------------- launch
extern "C" void kernel_launch(void* const* d_in, const int* in_sizes, int n_in,
                              void* d_out, int out_size)
{
    const int*   inp          = (const int*)d_in[0];
    const float* lut          = (const float*)d_in[1];
    const float* exp_scale    = (const float*)d_in[2];
    const float* exp_zero     = (const float*)d_in[3];
    const float* normed_scale = (const float*)d_in[4];
    const float* normed_zero  = (const float*)d_in[5];
    float*       out          = (float*)d_out;

    const int num_rows = out_size / S_LEN;          // 16384
    const long long n4 = (long long)out_size / 4;   // float4 count

    // 1. Evaluate the all-zero invariant on device (one tiny CTA).
    qsoftmax_predicate<<<1, 256>>>(lut, exp_scale, exp_zero, normed_scale, normed_zero);

    // 2. Fast path: write-only zero fill (self-disables if predicate false).
    //    148 SMs * 8 CTAs resident -> one wave per grid-stride chunk.
    qsoftmax_zero_fill<<<148 * 8, THREADS>>>(out, n4);

    // 3. General path: full computation (self-disables if predicate true).
    qsoftmax_general<<<num_rows, THREADS>>>(inp, lut, exp_scale, exp_zero,
                                            normed_scale, normed_zero, out);
}

// round 11
// speedup vs baseline: 2.2306x; 1.6986x over previous
#include <cuda_runtime.h>
#include <math.h>

// QSoftmax: out = clip(rint((LUT[inp]-exp_zero) * (1/rowsum(LUT[inp]) - 1/exp_zero)
//                           * (exp_scale*(1/exp_scale)/normed_scale) + normed_zero), 0, 255)
//
// R11: single fused kernel. Every CTA evaluates the all-zero invariant itself
// (LUT + scalars are L2-resident; the check doubles as the smem-LUT barrier):
//   (1) LUT[i] >= exp_zero for all i   (NaN entries fail)
//   (2) exp_zero > 0, 1/exp_zero finite
//   (3) multiplier finite and > 0
//   (4) normed_zero < 0.5
// Under these, rowsum >= 2048*exp_zero > exp_zero => b_zeroed < 0 =>
// r <= normed_zero < 0.5 => rint(r) <= 0 => clip == 0 for every element,
// independent of inp (inf LUT entries give r=-inf -> 0 as well).
// Fast path: write-only zero fill of this CTA's rows. Slow path: proven
// single-pass row softmax-quant (R8 body), 4 rows per CTA.

#define S_LEN 2048
#define THREADS 256
#define PER_THREAD 8            // 2048 / 256
#define ROWS_PER_CTA 4
#define ROW_STRIDE_I4 (S_LEN / 4)

__global__ __launch_bounds__(THREADS, 8)
void qsoftmax_fused(const int* __restrict__ inp,
                    const float* __restrict__ lut,
                    const float* __restrict__ exp_scale_p,
                    const float* __restrict__ exp_zero_p,
                    const float* __restrict__ normed_scale_p,
                    const float* __restrict__ normed_zero_p,
                    float* __restrict__ out)
{
    __shared__ float slut[256];
    __shared__ float swsum[2][THREADS / 32];

    const int tid  = threadIdx.x;
    const int lane = tid & 31;
    const int wid  = tid >> 5;

    // Load LUT (needed by both the predicate and the general path).
    const float v = lut[tid];
    slut[tid] = v;

    const float exp_scale    = exp_scale_p[0];
    const float exp_zero     = exp_zero_p[0];
    const float normed_scale = normed_scale_p[0];
    const float normed_zero  = normed_zero_p[0];

    const float inv_ez     = 1.0f / exp_zero;
    const float multiplier = exp_scale * (1.0f / exp_scale) / normed_scale;

    int ok = (v >= exp_zero)                       // false on NaN LUT entry
          && (exp_zero > 0.0f)
          && isfinite(inv_ez)
          && isfinite(multiplier) && (multiplier > 0.0f)
          && (normed_zero < 0.5f);                 // false on NaN normed_zero

    ok = __syncthreads_and(ok);                    // also fences slut[]

    const long long cta_base = (long long)blockIdx.x * (ROWS_PER_CTA * S_LEN);

    if (ok) {
        // ---- fast path: output is identically zero; no input read ----
        const float4 z = make_float4(0.0f, 0.0f, 0.0f, 0.0f);
        float4* o4 = reinterpret_cast<float4*>(out + cta_base) + tid;
        #pragma unroll
        for (int i = 0; i < (ROWS_PER_CTA * S_LEN) / (4 * THREADS); ++i)  // 8 x STG.128
            o4[i * THREADS] = z;
        return;
    }

    // ---- general path: full computation, 4 rows ----
    const long long base = cta_base + (long long)tid * PER_THREAD;
    const int4*  in4  = reinterpret_cast<const int4*>(inp + base);
    float4*      out4 = reinterpret_cast<float4*>(out + base);

    #pragma unroll
    for (int r = 0; r < ROWS_PER_CTA; ++r) {
        int4 a = in4[r * ROW_STRIDE_I4];
        int4 b = in4[r * ROW_STRIDE_I4 + 1];

        float e0 = slut[a.x], e1 = slut[a.y], e2 = slut[a.z], e3 = slut[a.w];
        float e4 = slut[b.x], e5 = slut[b.y], e6 = slut[b.z], e7 = slut[b.w];

        float s = ((e0 + e1) + (e2 + e3)) + ((e4 + e5) + (e6 + e7));

        #pragma unroll
        for (int off = 16; off > 0; off >>= 1)
            s += __shfl_xor_sync(0xffffffffu, s, off);

        if (lane == 0) swsum[r & 1][wid] = s;
        __syncthreads();

        const float* ws = swsum[r & 1];
        const float rowsum = ((ws[0] + ws[1]) + (ws[2] + ws[3]))
                           + ((ws[4] + ws[5]) + (ws[6] + ws[7]));

        const float factor = (1.0f / rowsum - inv_ez) * multiplier;

        float4 o0, o1;
        o0.x = fminf(fmaxf(rintf((e0 - exp_zero) * factor + normed_zero), 0.0f), 255.0f);
        o0.y = fminf(fmaxf(rintf((e1 - exp_zero) * factor + normed_zero), 0.0f), 255.0f);
        o0.z = fminf(fmaxf(rintf((e2 - exp_zero) * factor + normed_zero), 0.0f), 255.0f);
        o0.w = fminf(fmaxf(rintf((e3 - exp_zero) * factor + normed_zero), 0.0f), 255.0f);
        o1.x = fminf(fmaxf(rintf((e4 - exp_zero) * factor + normed_zero), 0.0f), 255.0f);
        o1.y = fminf(fmaxf(rintf((e5 - exp_zero) * factor + normed_zero), 0.0f), 255.0f);
        o1.z = fminf(fmaxf(rintf((e6 - exp_zero) * factor + normed_zero), 0.0f), 255.0f);
        o1.w = fminf(fmaxf(rintf((e7 - exp_zero) * factor + normed_zero), 0.0f), 255.0f);

        out4[r * ROW_STRIDE_I4]     = o0;
        out4[r * ROW_STRIDE_I4 + 1] = o1;
    }
}

extern "C" void kernel_launch(void* const* d_in, const int* in_sizes, int n_in,
                              void* d_out, int out_size)
{
    const int*   inp          = (const int*)d_in[0];
    const float* lut          = (const float*)d_in[1];
    const float* exp_scale    = (const float*)d_in[2];
    const float* exp_zero     = (const float*)d_in[3];
    const float* normed_scale = (const float*)d_in[4];
    const float* normed_zero  = (const float*)d_in[5];
    float*       out          = (float*)d_out;

    const int num_rows = out_size / S_LEN;             // 16384
    const int blocks   = num_rows / ROWS_PER_CTA;      // 4096
    qsoftmax_fused<<<blocks, THREADS>>>(inp, lut, exp_scale, exp_zero,
                                        normed_scale, normed_zero, out);
}